// round 9
// baseline (speedup 1.0000x reference)
#include <cuda_runtime.h>
#include <stdint.h>

#define NNODES   100000
#define NGRAPHS  128
#define HDIM     256

// Scratch (no allocation allowed). Static-initialized to zero; every launch
// restores agg to zero (pool zeroes each element after reading it), so no
// per-launch memset is needed.
__device__ float d_agg[NNODES];

// ---------------------------------------------------------------------------
// Kernel A: pure edge scatter-add.  agg[dst] += x[src].
// 16 edges/thread, front-batched int4 index loads (8x LDG.128),
// then 16 gathers, then 16 REDs.
// ---------------------------------------------------------------------------
__global__ void edge_kernel(const int* __restrict__ ei,
                            const float* __restrict__ x,
                            int E) {
    const int t = blockIdx.x * blockDim.x + threadIdx.x;
    const int i = t << 4;
    if (i + 16 <= E) {
        const int4* sp = reinterpret_cast<const int4*>(ei + i);
        const int4* dp = reinterpret_cast<const int4*>(ei + E + i);
        int4 s[4], d[4];
        #pragma unroll
        for (int j = 0; j < 4; j++) s[j] = __ldg(sp + j);
        #pragma unroll
        for (int j = 0; j < 4; j++) d[j] = __ldg(dp + j);
        float v[16];
        #pragma unroll
        for (int j = 0; j < 4; j++) {
            v[4 * j + 0] = __ldg(x + s[j].x);
            v[4 * j + 1] = __ldg(x + s[j].y);
            v[4 * j + 2] = __ldg(x + s[j].z);
            v[4 * j + 3] = __ldg(x + s[j].w);
        }
        #pragma unroll
        for (int j = 0; j < 4; j++) {
            atomicAdd(&d_agg[d[j].x], v[4 * j + 0]);
            atomicAdd(&d_agg[d[j].y], v[4 * j + 1]);
            atomicAdd(&d_agg[d[j].z], v[4 * j + 2]);
            atomicAdd(&d_agg[d[j].w], v[4 * j + 3]);
        }
    } else if (i < E) {
        for (int e = i; e < E; e++)
            atomicAdd(&d_agg[ei[E + e]], __ldg(x + ei[e]));
    }
}

// ---------------------------------------------------------------------------
// Kernel B (PDL secondary): one block per graph.
// Prologue (independent of kernel A, overlaps it under PDL):
//   - weight constants P/Nn + b_l==0 flag
//   - binary search of this graph's [start,end) in the sorted batch array
// Then cudaGridDependencySynchronize(), then the agg scan.  Each agg element
// is ZEROED immediately after being read, restoring the launch invariant.
// ---------------------------------------------------------------------------
__global__ __launch_bounds__(HDIM)
void pool_kernel(const int* __restrict__ batch,
                 const float* __restrict__ W_l,
                 const float* __restrict__ b_l,
                 const float* __restrict__ W_out,
                 const float* __restrict__ b_out,
                 float* __restrict__ out,
                 int N) {
    const int g = blockIdx.x;
    const int t = threadIdx.x;
    const int wid = t >> 5, lid = t & 31;

    // ---- prologue: weight-only constants ----
    const float w  = W_l[t];
    const float b  = b_l[t];
    const float wo = W_out[t];
    const float bo = b_out[0];
    const int allz = __syncthreads_and(b == 0.0f);
    float p = (w > 0.0f) ? wo * w : 0.0f;
    float n = (w < 0.0f) ? wo * w : 0.0f;
    #pragma unroll
    for (int off = 16; off; off >>= 1) {
        p += __shfl_xor_sync(0xffffffffu, p, off);
        n += __shfl_xor_sync(0xffffffffu, n, off);
    }
    __shared__ float sp8[8], sn8[8];
    __shared__ int   bounds[2];
    if (lid == 0) { sp8[wid] = p; sn8[wid] = n; }

    // ---- prologue: this graph's node range via binary search (batch only) ----
    if (t < 2) {
        const int target = g + t;            // t=0: lower_bound(g); t=1: lower_bound(g+1)
        int lo = 0, hi = N;
        while (lo < hi) {
            int m = (lo + hi) >> 1;
            if (__ldg(batch + m) < target) lo = m + 1; else hi = m;
        }
        bounds[t] = lo;
    }
    __syncthreads();
    float P = 0.0f, Nn = 0.0f;
    #pragma unroll
    for (int wI = 0; wI < 8; wI++) { P += sp8[wI]; Nn += sn8[wI]; }
    const int start = bounds[0];
    const int end   = bounds[1];
    const int len   = end - start;
    const float cnt = fmaxf((float)len, 1.0f);

    // ---- wait for edge kernel (no-op outside PDL) ----
    cudaGridDependencySynchronize();

    __shared__ float red0[8], red1[8];

    if (allz) {
        // fast path: Sum_k relu(v*w_k)*wo_k == P*max(v,0) + Nn*min(v,0)
        float sp = 0.0f, sn = 0.0f;
        const int a0 = min((start + 3) & ~3, end);   // first 16B-aligned idx
        const int a1 = max(end & ~3, a0);            // end of aligned region
        // scalar peel: [start,a0) and [a1,end), at most 3 each
        if (t < 4) {
            int hi = start + t;
            if (hi < a0) {
                float v = d_agg[hi];
                d_agg[hi] = 0.0f;
                sp += fmaxf(v, 0.0f);
                sn += fminf(v, 0.0f);
            }
            int ti = a1 + t;
            if (ti < end) {
                float v = d_agg[ti];
                d_agg[ti] = 0.0f;
                sp += fmaxf(v, 0.0f);
                sn += fminf(v, 0.0f);
            }
        }
        if (a1 > a0) {
            float4* va = reinterpret_cast<float4*>(d_agg + a0);
            const int nv = (a1 - a0) >> 2;
            const float4 z4 = make_float4(0.f, 0.f, 0.f, 0.f);
            for (int i = t; i < nv; i += HDIM) {
                float4 v = va[i];
                va[i] = z4;                            // restore zero invariant
                sp += fmaxf(v.x, 0.0f) + fmaxf(v.y, 0.0f)
                    + fmaxf(v.z, 0.0f) + fmaxf(v.w, 0.0f);
                sn += fminf(v.x, 0.0f) + fminf(v.y, 0.0f)
                    + fminf(v.z, 0.0f) + fminf(v.w, 0.0f);
            }
        }
        #pragma unroll
        for (int off = 16; off; off >>= 1) {
            sp += __shfl_xor_sync(0xffffffffu, sp, off);
            sn += __shfl_xor_sync(0xffffffffu, sn, off);
        }
        if (lid == 0) { red0[wid] = sp; red1[wid] = sn; }
        __syncthreads();
        if (t == 0) {
            float SP = 0.0f, SN = 0.0f;
            #pragma unroll
            for (int wI = 0; wI < 8; wI++) { SP += red0[wI]; SN += red1[wI]; }
            out[g] = fmaxf((P * SP + Nn * SN) / cnt + bo, 0.0f);
        }
        return;
    }

    // exact slow path (general b_l): one thread per feature
    float acc = 0.0f;
    __shared__ float sa[HDIM];
    for (int base = start; base < end; base += HDIM) {
        int nn = min(HDIM, end - base);
        __syncthreads();
        if (t < nn) {
            sa[t] = d_agg[base + t];
            d_agg[base + t] = 0.0f;                    // restore zero invariant
        }
        __syncthreads();
        float q0 = 0.f, q1 = 0.f, q2 = 0.f, q3 = 0.f;
        int j = 0;
        for (; j + 3 < nn; j += 4) {
            q0 += fmaxf(fmaf(sa[j],     w, b), 0.0f);
            q1 += fmaxf(fmaf(sa[j + 1], w, b), 0.0f);
            q2 += fmaxf(fmaf(sa[j + 2], w, b), 0.0f);
            q3 += fmaxf(fmaf(sa[j + 3], w, b), 0.0f);
        }
        for (; j < nn; j++)
            q0 += fmaxf(fmaf(sa[j], w, b), 0.0f);
        acc += (q0 + q1) + (q2 + q3);
    }
    float val = acc * wo / cnt;
    #pragma unroll
    for (int off = 16; off; off >>= 1)
        val += __shfl_xor_sync(0xffffffffu, val, off);
    if (lid == 0) red0[wid] = val;
    __syncthreads();
    if (t == 0) {
        float v = 0.0f;
        #pragma unroll
        for (int wI = 0; wI < 8; wI++) v += red0[wI];
        out[g] = fmaxf(v + bo, 0.0f);
    }
}

// ---------------------------------------------------------------------------
// inputs (metadata order):
//   0: x float32[N]  1: ei int32[2E]  2: batch int32[N]
//   3: W_l f32[256]  4: b_l f32[256]  5: W_out f32[256]  6: b_out f32[1]
// out: float32 [128]
// ---------------------------------------------------------------------------
extern "C" void kernel_launch(void* const* d_in, const int* in_sizes, int n_in,
                              void* d_out, int out_size) {
    const float* x     = (const float*)d_in[0];
    const int*   ei    = (const int*)d_in[1];
    const int*   batch = (const int*)d_in[2];
    const float* W_l   = (const float*)d_in[3];
    const float* b_l   = (const float*)d_in[4];
    const float* W_out = (const float*)d_in[5];
    const float* b_out = (const float*)d_in[6];
    float*       out   = (float*)d_out;

    const int N = in_sizes[0];
    const int E = in_sizes[1] / 2;

    const int threads    = 256;
    const int edgeWork   = (E + 15) / 16;
    const int edgeBlocks = (edgeWork + threads - 1) / threads;

    edge_kernel<<<edgeBlocks, threads>>>(ei, x, E);

    // Pool with programmatic dependent launch (prologue overlaps the edge
    // kernel); on ANY failure fall back to a plain launch (stream order still
    // correct, cudaGridDependencySynchronize is a no-op outside PDL).
    cudaError_t lerr = cudaErrorUnknown;
    {
        cudaLaunchConfig_t cfg = {};
        cfg.gridDim  = dim3(NGRAPHS, 1, 1);
        cfg.blockDim = dim3(HDIM, 1, 1);
        cfg.dynamicSmemBytes = 0;
        cfg.stream = 0;
        cudaLaunchAttribute attrs[1];
        attrs[0].id = cudaLaunchAttributeProgrammaticStreamSerialization;
        attrs[0].val.programmaticStreamSerializationAllowed = 1;
        cfg.attrs = attrs;
        cfg.numAttrs = 1;
        lerr = cudaLaunchKernelEx(&cfg, pool_kernel,
                                  batch, W_l, b_l, W_out, b_out, out, N);
    }
    if (lerr != cudaSuccess) {
        (void)cudaGetLastError();   // clear sticky error, then plain launch
        pool_kernel<<<NGRAPHS, HDIM>>>(batch, W_l, b_l, W_out, b_out, out, N);
    }
}

// round 12
// speedup vs baseline: 1.0195x; 1.0195x over previous
#include <cuda_runtime.h>
#include <stdint.h>

#define NNODES   100000
#define NGRAPHS  128
#define HDIM     256

// Scratch (no allocation allowed)
__device__ float d_agg[NNODES];
__device__ int   d_ctr;          // producer-completion counter (memset to 0)

__device__ __forceinline__ void red_release_add1(int* p) {
    asm volatile("red.release.gpu.global.add.s32 [%0], 1;" :: "l"(p) : "memory");
}
__device__ __forceinline__ int ld_acquire(const int* p) {
    int v;
    asm volatile("ld.acquire.gpu.global.s32 %0, [%1];" : "=r"(v) : "l"(p) : "memory");
    return v;
}
__device__ __forceinline__ float ldcg(const float* p) {
    float v;
    asm volatile("ld.global.cg.f32 %0, [%1];" : "=f"(v) : "l"(p));
    return v;
}
__device__ __forceinline__ float4 ldcg4(const float4* p) {
    float4 v;
    asm volatile("ld.global.cg.v4.f32 {%0,%1,%2,%3}, [%4];"
                 : "=f"(v.x), "=f"(v.y), "=f"(v.z), "=f"(v.w) : "l"(p));
    return v;
}

// ---------------------------------------------------------------------------
// Single fused kernel.
//   blocks [0, edgeBlocks)           : edge scatter  agg[dst] += x[src]
//                                      (8 edges/thread, int4 index loads);
//                                      then __syncthreads + ONE release-RMW.
//   blocks [edgeBlocks, +NGRAPHS)    : pool — prologue (weight constants +
//                                      binary search over sorted batch input,
//                                      all independent of the scatter), then
//                                      acquire-spin on d_ctr, then the agg
//                                      scan + output.  Grid-tail placement:
//                                      128 spinners never starve producers.
// ---------------------------------------------------------------------------
__global__ __launch_bounds__(256)
void fused_kernel(const int* __restrict__ ei,
                  const float* __restrict__ x,
                  const int* __restrict__ batch,
                  const float* __restrict__ W_l,
                  const float* __restrict__ b_l,
                  const float* __restrict__ W_out,
                  const float* __restrict__ b_out,
                  float* __restrict__ out,
                  int E, int N, int edgeBlocks) {
    const int bid = (int)blockIdx.x;

    if (bid < edgeBlocks) {
        // ------------------ edge scatter ------------------
        int t = bid * blockDim.x + threadIdx.x;
        int i = t << 3;
        if (i + 7 < E) {
            const int4* sp = reinterpret_cast<const int4*>(ei + i);
            const int4* dp = reinterpret_cast<const int4*>(ei + E + i);
            int4 s0 = __ldg(sp);
            int4 s1 = __ldg(sp + 1);
            int4 d0 = __ldg(dp);
            int4 d1 = __ldg(dp + 1);
            float v0 = __ldg(x + s0.x);
            float v1 = __ldg(x + s0.y);
            float v2 = __ldg(x + s0.z);
            float v3 = __ldg(x + s0.w);
            float v4 = __ldg(x + s1.x);
            float v5 = __ldg(x + s1.y);
            float v6 = __ldg(x + s1.z);
            float v7 = __ldg(x + s1.w);
            atomicAdd(&d_agg[d0.x], v0);
            atomicAdd(&d_agg[d0.y], v1);
            atomicAdd(&d_agg[d0.z], v2);
            atomicAdd(&d_agg[d0.w], v3);
            atomicAdd(&d_agg[d1.x], v4);
            atomicAdd(&d_agg[d1.y], v5);
            atomicAdd(&d_agg[d1.z], v6);
            atomicAdd(&d_agg[d1.w], v7);
        } else if (i < E) {
            for (int e = i; e < E; e++)
                atomicAdd(&d_agg[ei[E + e]], __ldg(x + ei[e]));
        }
        // All 256 threads' REDs are ordered before thread 0 by the barrier;
        // the release-RMW publishes them to the acquire-spinning pool blocks.
        __syncthreads();
        if (threadIdx.x == 0) red_release_add1(&d_ctr);
        return;
    }

    // ------------------ pool: one block per graph ------------------
    const int g = bid - edgeBlocks;
    const int t = threadIdx.x;
    const int wid = t >> 5, lid = t & 31;

    // prologue (independent of the scatter): weight constants
    const float w  = W_l[t];
    const float b  = b_l[t];
    const float wo = W_out[t];
    const float bo = b_out[0];
    const int allz = __syncthreads_and(b == 0.0f);
    float p = (w > 0.0f) ? wo * w : 0.0f;
    float n = (w < 0.0f) ? wo * w : 0.0f;
    #pragma unroll
    for (int off = 16; off; off >>= 1) {
        p += __shfl_xor_sync(0xffffffffu, p, off);
        n += __shfl_xor_sync(0xffffffffu, n, off);
    }
    __shared__ float sp8[8], sn8[8];
    __shared__ int   bounds[2];
    if (lid == 0) { sp8[wid] = p; sn8[wid] = n; }

    // prologue: graph bounds via binary search on the (input) batch array
    if (t < 2) {
        const int target = g + t;
        int lo = 0, hi = N;
        while (lo < hi) {
            int m = (lo + hi) >> 1;
            if (__ldg(batch + m) < target) lo = m + 1; else hi = m;
        }
        bounds[t] = lo;
    }
    __syncthreads();
    float P = 0.0f, Nn = 0.0f;
    #pragma unroll
    for (int wI = 0; wI < 8; wI++) { P += sp8[wI]; Nn += sn8[wI]; }
    const int start = bounds[0];
    const int end   = bounds[1];
    const int len   = end - start;
    const float cnt = fmaxf((float)len, 1.0f);

    // wait for all producer blocks (acquire pairs with their release-RMW)
    if (t == 0) {
        while (ld_acquire(&d_ctr) < edgeBlocks) __nanosleep(64);
    }
    __syncthreads();

    __shared__ float red0[8], red1[8];

    if (allz) {
        // fast path: Sum_k wo_k*relu(v*w_k) == P*max(v,0) + Nn*min(v,0)
        float sp = 0.0f, sn = 0.0f;
        const int a0 = min((start + 3) & ~3, end);   // first 16B-aligned idx
        const int a1 = max(end & ~3, a0);            // end of aligned region
        if (t < 4) {                                  // head peel (<=3)
            int hh = start + t;
            if (hh < a0) {
                float v = ldcg(&d_agg[hh]);
                sp += fmaxf(v, 0.0f);
                sn += fminf(v, 0.0f);
            }
        } else if (t < 8) {                           // tail peel (<=3)
            int ti = a1 + (t - 4);
            if (ti < end) {
                float v = ldcg(&d_agg[ti]);
                sp += fmaxf(v, 0.0f);
                sn += fminf(v, 0.0f);
            }
        }
        if (a1 > a0) {
            const float4* va = reinterpret_cast<const float4*>(d_agg + a0);
            const int nv = (a1 - a0) >> 2;
            for (int i = t; i < nv; i += HDIM) {
                float4 v = ldcg4(va + i);
                sp += fmaxf(v.x, 0.0f) + fmaxf(v.y, 0.0f)
                    + fmaxf(v.z, 0.0f) + fmaxf(v.w, 0.0f);
                sn += fminf(v.x, 0.0f) + fminf(v.y, 0.0f)
                    + fminf(v.z, 0.0f) + fminf(v.w, 0.0f);
            }
        }
        #pragma unroll
        for (int off = 16; off; off >>= 1) {
            sp += __shfl_xor_sync(0xffffffffu, sp, off);
            sn += __shfl_xor_sync(0xffffffffu, sn, off);
        }
        if (lid == 0) { red0[wid] = sp; red1[wid] = sn; }
        __syncthreads();
        if (t == 0) {
            float SP = 0.0f, SN = 0.0f;
            #pragma unroll
            for (int wI = 0; wI < 8; wI++) { SP += red0[wI]; SN += red1[wI]; }
            out[g] = fmaxf((P * SP + Nn * SN) / cnt + bo, 0.0f);
        }
        return;
    }

    // exact slow path (general b_l): one thread per feature
    float acc = 0.0f;
    __shared__ float sa[HDIM];
    for (int base = start; base < end; base += HDIM) {
        int nn = min(HDIM, end - base);
        __syncthreads();
        if (t < nn) sa[t] = ldcg(&d_agg[base + t]);
        __syncthreads();
        float q0 = 0.f, q1 = 0.f, q2 = 0.f, q3 = 0.f;
        int j = 0;
        for (; j + 3 < nn; j += 4) {
            q0 += fmaxf(fmaf(sa[j],     w, b), 0.0f);
            q1 += fmaxf(fmaf(sa[j + 1], w, b), 0.0f);
            q2 += fmaxf(fmaf(sa[j + 2], w, b), 0.0f);
            q3 += fmaxf(fmaf(sa[j + 3], w, b), 0.0f);
        }
        for (; j < nn; j++)
            q0 += fmaxf(fmaf(sa[j], w, b), 0.0f);
        acc += (q0 + q1) + (q2 + q3);
    }
    float val = acc * wo / cnt;
    #pragma unroll
    for (int off = 16; off; off >>= 1)
        val += __shfl_xor_sync(0xffffffffu, val, off);
    if (lid == 0) red0[wid] = val;
    __syncthreads();
    if (t == 0) {
        float v = 0.0f;
        #pragma unroll
        for (int wI = 0; wI < 8; wI++) v += red0[wI];
        out[g] = fmaxf(v + bo, 0.0f);
    }
}

// ---------------------------------------------------------------------------
// inputs (metadata order):
//   0: x float32[N]  1: ei int32[2E]  2: batch int32[N]
//   3: W_l f32[256]  4: b_l f32[256]  5: W_out f32[256]  6: b_out f32[1]
// out: float32 [128]
// ---------------------------------------------------------------------------
extern "C" void kernel_launch(void* const* d_in, const int* in_sizes, int n_in,
                              void* d_out, int out_size) {
    const float* x     = (const float*)d_in[0];
    const int*   ei    = (const int*)d_in[1];
    const int*   batch = (const int*)d_in[2];
    const float* W_l   = (const float*)d_in[3];
    const float* b_l   = (const float*)d_in[4];
    const float* W_out = (const float*)d_in[5];
    const float* b_out = (const float*)d_in[6];
    float*       out   = (float*)d_out;

    const int N = in_sizes[0];
    const int E = in_sizes[1] / 2;

    // zero agg + counter via memset nodes (graph-capturable)
    void* aggp = nullptr;
    cudaGetSymbolAddress(&aggp, d_agg);
    cudaMemsetAsync(aggp, 0, (size_t)N * sizeof(float), 0);
    void* ctrp = nullptr;
    cudaGetSymbolAddress(&ctrp, d_ctr);
    cudaMemsetAsync(ctrp, 0, sizeof(int), 0);

    const int threads    = 256;
    const int edgeWork   = (E + 7) / 8;
    const int edgeBlocks = (edgeWork + threads - 1) / threads;
    const int grid       = edgeBlocks + NGRAPHS;

    fused_kernel<<<grid, threads>>>(ei, x, batch, W_l, b_l, W_out, b_out, out,
                                    E, N, edgeBlocks);
}

// round 13
// speedup vs baseline: 1.1645x; 1.1422x over previous
#include <cuda_runtime.h>
#include <stdint.h>

#define NNODES   100000
#define NGRAPHS  128
#define HDIM     256

// Scratch (no allocation allowed). Static-init zero; the pool kernel restores
// every element to zero after reading it, so agg is zero at every
// kernel_launch entry without a per-launch memset.
__device__ float d_agg[NNODES];
__device__ int   d_starts[NGRAPHS + 1];

// ---------------------------------------------------------------------------
// Kernel A: edge scatter-add + boundary detection (independent; boundary
// blocks ride free inside the LSU-bound edge scatter).
// ---------------------------------------------------------------------------
__global__ void edge_boundary_kernel(const int* __restrict__ ei,
                                     const float* __restrict__ x,
                                     const int* __restrict__ batch,
                                     int E, int N, int edgeBlocks) {
    const int bid = (int)blockIdx.x;
    if (bid < edgeBlocks) {
        // ---- edge scatter: 8 edges/thread, front-batched int4 index loads ----
        int t = bid * blockDim.x + threadIdx.x;
        int i = t << 3;
        if (i + 7 < E) {
            const int4* sp = reinterpret_cast<const int4*>(ei + i);
            const int4* dp = reinterpret_cast<const int4*>(ei + E + i);
            int4 s0 = __ldg(sp);
            int4 s1 = __ldg(sp + 1);
            int4 d0 = __ldg(dp);
            int4 d1 = __ldg(dp + 1);
            float v0 = __ldg(x + s0.x);
            float v1 = __ldg(x + s0.y);
            float v2 = __ldg(x + s0.z);
            float v3 = __ldg(x + s0.w);
            float v4 = __ldg(x + s1.x);
            float v5 = __ldg(x + s1.y);
            float v6 = __ldg(x + s1.z);
            float v7 = __ldg(x + s1.w);
            atomicAdd(&d_agg[d0.x], v0);
            atomicAdd(&d_agg[d0.y], v1);
            atomicAdd(&d_agg[d0.z], v2);
            atomicAdd(&d_agg[d0.w], v3);
            atomicAdd(&d_agg[d1.x], v4);
            atomicAdd(&d_agg[d1.y], v5);
            atomicAdd(&d_agg[d1.z], v6);
            atomicAdd(&d_agg[d1.w], v7);
        } else if (i < E) {
            for (int e = i; e < E; e++)
                atomicAdd(&d_agg[ei[E + e]], __ldg(x + ei[e]));
        }
    } else {
        // ---- boundary detection on sorted batch, 4 nodes/thread ----
        int t    = (bid - edgeBlocks) * blockDim.x + threadIdx.x;
        int base = t << 2;
        if (base >= N) return;
        int b0, b1, b2, b3;
        if (base + 3 < N) {
            int4 v = __ldg(reinterpret_cast<const int4*>(batch + base));
            b0 = v.x; b1 = v.y; b2 = v.z; b3 = v.w;
        } else {
            b0 = batch[base];
            b1 = (base + 1 < N) ? batch[base + 1] : b0;
            b2 = (base + 2 < N) ? batch[base + 2] : b1;
            b3 = (base + 3 < N) ? batch[base + 3] : b2;
        }
        int prev = (base == 0) ? -1 : __ldg(batch + base - 1);
        #pragma unroll
        for (int e = 0; e < 4; e++) {
            int idx = base + e;
            int b = (e == 0) ? b0 : (e == 1) ? b1 : (e == 2) ? b2 : b3;
            if (idx < N) {
                for (int g = prev + 1; g <= b; g++) d_starts[g] = idx;
                prev = b;
                if (idx == N - 1)
                    for (int g = b + 1; g <= NGRAPHS; g++) d_starts[g] = N;
            }
        }
    }
}

// ---------------------------------------------------------------------------
// Kernel B (PDL secondary, no trigger — R8-proven launch path): one block per
// graph.  Weight-only prologue; then the grid-dependency sync gates the
// d_starts read and the agg scan.  Every agg element is ZEROED right after
// being read, restoring the launch invariant (replaces the memset).
// ---------------------------------------------------------------------------
__global__ __launch_bounds__(HDIM)
void pool_kernel(const float* __restrict__ W_l,
                 const float* __restrict__ b_l,
                 const float* __restrict__ W_out,
                 const float* __restrict__ b_out,
                 float* __restrict__ out) {
    const int g = blockIdx.x;
    const int t = threadIdx.x;
    const int wid = t >> 5, lid = t & 31;

    // ---- prologue: weight-only constants ----
    const float w  = W_l[t];
    const float b  = b_l[t];
    const float wo = W_out[t];
    const float bo = b_out[0];
    const int allz = __syncthreads_and(b == 0.0f);
    float p = (w > 0.0f) ? wo * w : 0.0f;
    float n = (w < 0.0f) ? wo * w : 0.0f;
    #pragma unroll
    for (int off = 16; off; off >>= 1) {
        p += __shfl_xor_sync(0xffffffffu, p, off);
        n += __shfl_xor_sync(0xffffffffu, n, off);
    }
    __shared__ float sp8[8], sn8[8];
    if (lid == 0) { sp8[wid] = p; sn8[wid] = n; }
    __syncthreads();
    float P = 0.0f, Nn = 0.0f;
    #pragma unroll
    for (int wI = 0; wI < 8; wI++) { P += sp8[wI]; Nn += sn8[wI]; }

    // ---- wait for kernel A (no-op outside PDL) ----
#if __CUDA_ARCH__ >= 900
    cudaGridDependencySynchronize();
#endif

    const int start = d_starts[g];
    const int end   = d_starts[g + 1];
    const int len   = end - start;
    const float cnt = fmaxf((float)len, 1.0f);

    __shared__ float red0[8], red1[8];

    if (allz) {
        // fast path: Sum_k wo_k*relu(v*w_k) == P*max(v,0) + Nn*min(v,0)
        float sp = 0.0f, sn = 0.0f;
        const int a0 = min((start + 3) & ~3, end);   // first 16B-aligned idx
        const int a1 = max(end & ~3, a0);            // end of aligned region
        if (t < 4) {                                  // head peel (<=3)
            int hh = start + t;
            if (hh < a0) {
                float v = d_agg[hh];
                d_agg[hh] = 0.0f;
                sp += fmaxf(v, 0.0f);
                sn += fminf(v, 0.0f);
            }
        } else if (t < 8) {                           // tail peel (<=3)
            int ti = a1 + (t - 4);
            if (ti < end) {
                float v = d_agg[ti];
                d_agg[ti] = 0.0f;
                sp += fmaxf(v, 0.0f);
                sn += fminf(v, 0.0f);
            }
        }
        if (a1 > a0) {
            float4* va = reinterpret_cast<float4*>(d_agg + a0);
            const int nv = (a1 - a0) >> 2;
            const float4 z4 = make_float4(0.f, 0.f, 0.f, 0.f);
            for (int i = t; i < nv; i += HDIM) {
                float4 v = va[i];
                va[i] = z4;                            // restore zero invariant
                sp += fmaxf(v.x, 0.0f) + fmaxf(v.y, 0.0f)
                    + fmaxf(v.z, 0.0f) + fmaxf(v.w, 0.0f);
                sn += fminf(v.x, 0.0f) + fminf(v.y, 0.0f)
                    + fminf(v.z, 0.0f) + fminf(v.w, 0.0f);
            }
        }
        #pragma unroll
        for (int off = 16; off; off >>= 1) {
            sp += __shfl_xor_sync(0xffffffffu, sp, off);
            sn += __shfl_xor_sync(0xffffffffu, sn, off);
        }
        if (lid == 0) { red0[wid] = sp; red1[wid] = sn; }
        __syncthreads();
        if (t == 0) {
            float SP = 0.0f, SN = 0.0f;
            #pragma unroll
            for (int wI = 0; wI < 8; wI++) { SP += red0[wI]; SN += red1[wI]; }
            out[g] = fmaxf((P * SP + Nn * SN) / cnt + bo, 0.0f);
        }
        return;
    }

    // exact slow path (general b_l): one thread per feature
    float acc = 0.0f;
    __shared__ float sa[HDIM];
    for (int base = start; base < end; base += HDIM) {
        int nn = min(HDIM, end - base);
        __syncthreads();
        if (t < nn) {
            sa[t] = d_agg[base + t];
            d_agg[base + t] = 0.0f;                    // restore zero invariant
        }
        __syncthreads();
        float q0 = 0.f, q1 = 0.f, q2 = 0.f, q3 = 0.f;
        int j = 0;
        for (; j + 3 < nn; j += 4) {
            q0 += fmaxf(fmaf(sa[j],     w, b), 0.0f);
            q1 += fmaxf(fmaf(sa[j + 1], w, b), 0.0f);
            q2 += fmaxf(fmaf(sa[j + 2], w, b), 0.0f);
            q3 += fmaxf(fmaf(sa[j + 3], w, b), 0.0f);
        }
        for (; j < nn; j++)
            q0 += fmaxf(fmaf(sa[j], w, b), 0.0f);
        acc += (q0 + q1) + (q2 + q3);
    }
    float val = acc * wo / cnt;
    #pragma unroll
    for (int off = 16; off; off >>= 1)
        val += __shfl_xor_sync(0xffffffffu, val, off);
    if (lid == 0) red0[wid] = val;
    __syncthreads();
    if (t == 0) {
        float v = 0.0f;
        #pragma unroll
        for (int wI = 0; wI < 8; wI++) v += red0[wI];
        out[g] = fmaxf(v + bo, 0.0f);
    }
}

// ---------------------------------------------------------------------------
// inputs (metadata order):
//   0: x float32[N]  1: ei int32[2E]  2: batch int32[N]
//   3: W_l f32[256]  4: b_l f32[256]  5: W_out f32[256]  6: b_out f32[1]
// out: float32 [128]
// ---------------------------------------------------------------------------
extern "C" void kernel_launch(void* const* d_in, const int* in_sizes, int n_in,
                              void* d_out, int out_size) {
    const float* x     = (const float*)d_in[0];
    const int*   ei    = (const int*)d_in[1];
    const int*   batch = (const int*)d_in[2];
    const float* W_l   = (const float*)d_in[3];
    const float* b_l   = (const float*)d_in[4];
    const float* W_out = (const float*)d_in[5];
    const float* b_out = (const float*)d_in[6];
    float*       out   = (float*)d_out;

    const int N = in_sizes[0];
    const int E = in_sizes[1] / 2;

    const int threads    = 256;
    const int edgeWork   = (E + 7) / 8;
    const int edgeBlocks = (edgeWork + threads - 1) / threads;
    const int bndThreads = (N + 3) / 4;
    const int bndBlocks  = (bndThreads + threads - 1) / threads;

    // no memset: agg's zero invariant is maintained by the pool kernel
    edge_boundary_kernel<<<edgeBlocks + bndBlocks, threads>>>(
        ei, x, batch, E, N, edgeBlocks);

    // Pool via the R8-proven PDL launch path (no trigger); fall back to a
    // plain launch on any failure (stream order still correct).
    cudaError_t lerr = cudaErrorUnknown;
    {
        cudaLaunchConfig_t cfg = {};
        cfg.gridDim  = dim3(NGRAPHS, 1, 1);
        cfg.blockDim = dim3(HDIM, 1, 1);
        cfg.dynamicSmemBytes = 0;
        cfg.stream = 0;
        cudaLaunchAttribute attrs[1];
        attrs[0].id = cudaLaunchAttributeProgrammaticStreamSerialization;
        attrs[0].val.programmaticStreamSerializationAllowed = 1;
        cfg.attrs = attrs;
        cfg.numAttrs = 1;
        lerr = cudaLaunchKernelEx(&cfg, pool_kernel, W_l, b_l, W_out, b_out, out);
    }
    if (lerr != cudaSuccess) {
        (void)cudaGetLastError();   // clear sticky error, then plain launch
        pool_kernel<<<NGRAPHS, HDIM>>>(W_l, b_l, W_out, b_out, out);
    }
}